// round 17
// baseline (speedup 1.0000x reference)
#include <cuda_runtime.h>
#include <cuda_bf16.h>

#define G_SIZE 4096
#define B_SIZE 16
#define NCH 15
#define D_MAX 20          // Taylor degree: terms d = 0..20
#define ND (D_MAX + 1)    // 21
#define NDG (ND / 3)      // 7 degree-groups of 3
#define NSPL 4
#define LPER (G_SIZE / NSPL)   // 1024

// Split-innermost layout: Mo_part[((c*ND + d)*B_SIZE + b)*NSPL + sp]
__device__ float Mo_part[NCH * ND * B_SIZE * NSPL];

#define LOG2E 1.4426950408889634f

__device__ __forceinline__ float ex2f(float x) {
    float r; asm("ex2.approx.ftz.f32 %0, %1;" : "=f"(r) : "f"(x)); return r;
}

// gl^e by binary exponentiation (e uniform across CTA -> no divergence)
__device__ __forceinline__ float powu(float g, int e) {
    float p = 1.0f, b = g;
#pragma unroll
    for (int k = 0; k < 5; ++k) {            // e <= 20 < 32
        if (e & 1) p *= b;
        b *= b;
        e >>= 1;
    }
    return p;
}

// Moments partials (R15 config, proven equal-best). Triggers PDL completion after stores.
// grid = (7 degree-groups, 15 channels, 4 l-splits) = 420 CTAs, 256 threads (8 warps x 2 b)
__global__ __launch_bounds__(256) void moments_kernel(const float* __restrict__ xi,
                                                      const float* __restrict__ grid,
                                                      const float* __restrict__ gw,
                                                      const float* __restrict__ density) {
    __shared__ __align__(16) float prod[3][LPER];      // 12 KB
    const int dg = blockIdx.x;      // 0..6 -> degrees 3dg..3dg+2
    const int c  = blockIdx.y;
    const int sp = blockIdx.z;      // 0..3
    const int tid = threadIdx.x;
    const int l0 = sp * LPER;

    const float xi_t = 1.0f + ex2f(-xi[c] * LOG2E);
    const float cg = -xi_t * LOG2E;
    const int e0 = 3 * dg;

    // Stage: each of 256 threads builds 4 l-entries for all 3 degree rows
    {
        float4 g4 = ((const float4*)(grid + l0))[tid];
        float4 w4 = ((const float4*)(gw + l0))[tid];
        float4 r0, r1, r2;
        {
            float g = g4.x, F = w4.x * ex2f(g * g * cg), p = powu(g, e0);
            r0.x = F * p; p *= g; r1.x = F * p; p *= g; r2.x = F * p;
        }
        {
            float g = g4.y, F = w4.y * ex2f(g * g * cg), p = powu(g, e0);
            r0.y = F * p; p *= g; r1.y = F * p; p *= g; r2.y = F * p;
        }
        {
            float g = g4.z, F = w4.z * ex2f(g * g * cg), p = powu(g, e0);
            r0.z = F * p; p *= g; r1.z = F * p; p *= g; r2.z = F * p;
        }
        {
            float g = g4.w, F = w4.w * ex2f(g * g * cg), p = powu(g, e0);
            r0.w = F * p; p *= g; r1.w = F * p; p *= g; r2.w = F * p;
        }
        ((float4*)prod[0])[tid] = r0;
        ((float4*)prod[1])[tid] = r1;
        ((float4*)prod[2])[tid] = r2;
    }
    __syncthreads();

    const int wid = tid >> 5, lane = tid & 31;

    float t = 2.0f * xi_t;
    float coef0 = 1.0f;
    for (int i = 1; i <= e0; ++i) coef0 = coef0 * t / (float)i;
    float coef1 = coef0 * t / (float)(e0 + 1);
    float coef2 = coef1 * t / (float)(e0 + 2);

    const float4* p0 = (const float4*)prod[0];
    const float4* p1 = (const float4*)prod[1];
    const float4* p2 = (const float4*)prod[2];

    // Merged pass: both batches (2*wid, 2*wid+1) in one loop.
    const int ba = 2 * wid, bb2 = 2 * wid + 1;
    const float4* dra = (const float4*)(density + ba * G_SIZE + l0);
    const float4* drb = (const float4*)(density + bb2 * G_SIZE + l0);

    float s0a = 0.f, s1a = 0.f, s2a = 0.f, u0a = 0.f, u1a = 0.f, u2a = 0.f;
    float s0b = 0.f, s1b = 0.f, s2b = 0.f, u0b = 0.f, u1b = 0.f, u2b = 0.f;
#pragma unroll
    for (int i = 0; i < LPER / 4 / 32; ++i) {          // 8 iters, fully unrolled
        int ix = lane + i * 32;
        float4 da = dra[ix];
        float4 db = drb[ix];
        float4 a0 = p0[ix], a1 = p1[ix], a2 = p2[ix];
        s0a += da.x * a0.x + da.y * a0.y;  u0a += da.z * a0.z + da.w * a0.w;
        s1a += da.x * a1.x + da.y * a1.y;  u1a += da.z * a1.z + da.w * a1.w;
        s2a += da.x * a2.x + da.y * a2.y;  u2a += da.z * a2.z + da.w * a2.w;
        s0b += db.x * a0.x + db.y * a0.y;  u0b += db.z * a0.z + db.w * a0.w;
        s1b += db.x * a1.x + db.y * a1.y;  u1b += db.z * a1.z + db.w * a1.w;
        s2b += db.x * a2.x + db.y * a2.y;  u2b += db.z * a2.z + db.w * a2.w;
    }
    s0a += u0a; s1a += u1a; s2a += u2a;
    s0b += u0b; s1b += u1b; s2b += u2b;
#pragma unroll
    for (int o = 16; o; o >>= 1) {
        s0a += __shfl_xor_sync(0xffffffffu, s0a, o);
        s1a += __shfl_xor_sync(0xffffffffu, s1a, o);
        s2a += __shfl_xor_sync(0xffffffffu, s2a, o);
        s0b += __shfl_xor_sync(0xffffffffu, s0b, o);
        s1b += __shfl_xor_sync(0xffffffffu, s1b, o);
        s2b += __shfl_xor_sync(0xffffffffu, s2b, o);
    }
    if (lane == 0) {
        Mo_part[((c * ND + e0 + 0) * B_SIZE + ba) * NSPL + sp] = s0a * coef0;
        Mo_part[((c * ND + e0 + 1) * B_SIZE + ba) * NSPL + sp] = s1a * coef1;
        Mo_part[((c * ND + e0 + 2) * B_SIZE + ba) * NSPL + sp] = s2a * coef2;
        Mo_part[((c * ND + e0 + 0) * B_SIZE + bb2) * NSPL + sp] = s0b * coef0;
        Mo_part[((c * ND + e0 + 1) * B_SIZE + bb2) * NSPL + sp] = s1b * coef1;
        Mo_part[((c * ND + e0 + 2) * B_SIZE + bb2) * NSPL + sp] = s2b * coef2;
    }

    // PDL: signal that this CTA's Mo_part writes are done (release early to secondary).
    cudaTriggerProgrammaticLaunchCompletion();
}

// Output (R11-proven geometry) with PDL: everything Mo-independent runs BEFORE
// cudaGridDependencySynchronize(), overlapping with moments' execution.
// 512 threads = 4 batch-groups x 128 m, grid = (32 m-blocks, 16 channels) = 512 CTAs.
__global__ __launch_bounds__(512) void output_kernel(const float* __restrict__ xi,
                                                     const float* __restrict__ grid,
                                                     const float* __restrict__ density,
                                                     float* __restrict__ out) {
    const int c = blockIdx.y;
    const int tid = threadIdx.x;
    const int bg = tid >> 7;          // 0..3 -> batches 4*bg..4*bg+3
    const int m = blockIdx.x * 128 + (tid & 127);

    if (c == NCH) {   // raw density channel — fully independent of moments
#pragma unroll
        for (int q = 0; q < 4; ++q) {
            int b = 4 * bg + q;
            out[(b * 16 + NCH) * G_SIZE + m] = density[b * G_SIZE + m];
        }
        return;
    }

    // Mo-independent prologue (overlaps with moments under PDL)
    float gm = grid[m];
    float xi_t = 1.0f + ex2f(-xi[c] * LOG2E);
    float scale = 0.5f * xi_t * ex2f(-gm * gm * xi_t * LOG2E);

    // Wait for moments' Mo_part writes to be visible
    cudaGridDependencySynchronize();

    __shared__ __align__(16) float sMo[ND * B_SIZE];   // 336 floats
    if (tid < ND * B_SIZE) {
        float4 v = ((const float4*)Mo_part)[c * ND * B_SIZE + tid];
        sMo[tid] = (v.x + v.y) + (v.z + v.w);
    }
    __syncthreads();

    // 4 independent Horner chains; one broadcast LDS.128 per degree step.
    const float4* col = (const float4*)(sMo) + bg;     // row d -> col[d*4]
    float4 w = col[D_MAX * 4];
    float a0 = w.x, a1 = w.y, a2 = w.z, a3 = w.w;
#pragma unroll
    for (int d = D_MAX - 1; d >= 0; --d) {
        float4 v = col[d * 4];
        a0 = a0 * gm + v.x;
        a1 = a1 * gm + v.y;
        a2 = a2 * gm + v.z;
        a3 = a3 * gm + v.w;
    }

    const int b0 = 4 * bg;
    out[((b0 + 0) * 16 + c) * G_SIZE + m] = a0 * scale;
    out[((b0 + 1) * 16 + c) * G_SIZE + m] = a1 * scale;
    out[((b0 + 2) * 16 + c) * G_SIZE + m] = a2 * scale;
    out[((b0 + 3) * 16 + c) * G_SIZE + m] = a3 * scale;
}

extern "C" void kernel_launch(void* const* d_in, const int* in_sizes, int n_in,
                              void* d_out, int out_size) {
    const float* density = (const float*)d_in[0];  // (16,1,4096)
    const float* xi      = (const float*)d_in[1];  // (15,)
    const float* grid    = (const float*)d_in[2];  // (4096,)
    const float* gw      = (const float*)d_in[3];  // (4096,)
    float* out = (float*)d_out;                    // (16,16,4096)

    moments_kernel<<<dim3(NDG, NCH, NSPL), 256>>>(xi, grid, gw, density);

    // Launch output with Programmatic Stream Serialization: it may begin executing
    // while moments is still running; correctness via cudaGridDependencySynchronize().
    cudaLaunchConfig_t cfg = {};
    cfg.gridDim = dim3(G_SIZE / 128, NCH + 1);
    cfg.blockDim = dim3(512);
    cfg.dynamicSmemBytes = 0;
    cudaLaunchAttribute attrs[1];
    attrs[0].id = cudaLaunchAttributeProgrammaticStreamSerialization;
    attrs[0].val.programmaticStreamSerializationAllowed = 1;
    cfg.attrs = attrs;
    cfg.numAttrs = 1;
    cudaLaunchKernelEx(&cfg, output_kernel, xi, grid, density, out);
}